// round 16
// baseline (speedup 1.0000x reference)
#include <cuda_runtime.h>
#include <cuda_bf16.h>
#include <math.h>
#include <stdint.h>

// Problem dims (fixed by the reference)
#define TT  16384   // tokens = B*S
#define HH  1024    // hidden
#define EE  8       // routed experts
#define KK  2       // top-k
#define DEE 128     // routed expert hidden
#define DSS 512     // shared expert hidden
#define NSLOT (TT*KK)

typedef __nv_bfloat16 bf16;

// ---------------- device scratch (ONLY referenced inside kernels) ----------------
__device__ int   g_cnt[EE];
__device__ int   g_off[EE + 1];
__device__ int   g_pos[EE];
__device__ int   g_top_idx[TT * KK];
__device__ float g_top_w[TT * KK];
__device__ int   g_tok[NSLOT];
__device__ float g_wt[NSLOT];
__device__ int   g_slot[NSLOT];

// pre-split bf16 hi/lo tensors (16B aligned for vector access)
__device__ __align__(16) bf16 gxh[TT * HH];
__device__ __align__(16) bf16 gxl[TT * HH];
__device__ __align__(16) bf16 gw_s1h[DSS * HH];
__device__ __align__(16) bf16 gw_s1l[DSS * HH];
__device__ __align__(16) bf16 gw_s2h[HH * DSS];
__device__ __align__(16) bf16 gw_s2l[HH * DSS];
__device__ __align__(16) bf16 gw_1h[EE * DEE * HH];
__device__ __align__(16) bf16 gw_1l[EE * DEE * HH];
__device__ __align__(16) bf16 gw_2h[EE * HH * DEE];
__device__ __align__(16) bf16 gw_2l[EE * HH * DEE];
__device__ __align__(16) bf16 ghsh[TT * DSS];
__device__ __align__(16) bf16 ghsl[TT * DSS];
__device__ __align__(16) bf16 gh1h[NSLOT * DEE];
__device__ __align__(16) bf16 gh1l[NSLOT * DEE];
__device__ float g_y2[(size_t)NSLOT * HH];

// ---------------- helpers ----------------
// pack two floats into bf16x2: f0 -> low half, f1 -> high half
__device__ __forceinline__ uint32_t pack_bf2(float f0, float f1) {
    uint32_t r;
    asm("cvt.rn.bf16x2.f32 %0, %1, %2;" : "=r"(r) : "f"(f1), "f"(f0));
    return r;
}
// hi/lo split of a float pair
__device__ __forceinline__ void split2(float f0, float f1, uint32_t& hp, uint32_t& lp) {
    hp = pack_bf2(f0, f1);
    float h0 = __uint_as_float(hp << 16);
    float h1 = __uint_as_float(hp & 0xFFFF0000u);
    lp = pack_bf2(f0 - h0, f1 - h1);
}

#define MMABF16(d, a, b) \
    asm volatile("mma.sync.aligned.m16n8k16.row.col.f32.bf16.bf16.f32 " \
                 "{%0,%1,%2,%3}, {%4,%5,%6,%7}, {%8,%9}, {%0,%1,%2,%3};" \
                 : "+f"((d)[0]), "+f"((d)[1]), "+f"((d)[2]), "+f"((d)[3]) \
                 : "r"((a)[0]), "r"((a)[1]), "r"((a)[2]), "r"((a)[3]), \
                   "r"((b)[0]), "r"((b)[1]))

// ---------------- small kernels (unchanged, proven) ----------------
__global__ void k_zero_cnt() {
    if (threadIdx.x < EE) g_cnt[threadIdx.x] = 0;
}

__global__ void k_gate(const float* __restrict__ x, const float* __restrict__ Wg) {
    int warp = (blockIdx.x * blockDim.x + threadIdx.x) >> 5;
    int lane = threadIdx.x & 31;
    if (warp >= TT) return;
    const float* xr = x + (size_t)warp * HH;
    float acc[EE];
#pragma unroll
    for (int e = 0; e < EE; e++) acc[e] = 0.f;
    for (int j = lane; j < HH; j += 32) {
        float xv = xr[j];
#pragma unroll
        for (int e = 0; e < EE; e++) acc[e] += xv * Wg[e * HH + j];
    }
#pragma unroll
    for (int e = 0; e < EE; e++) {
#pragma unroll
        for (int off = 16; off; off >>= 1)
            acc[e] += __shfl_xor_sync(0xFFFFFFFFu, acc[e], off);
    }
    if (lane == 0) {
        float mx = acc[0];
#pragma unroll
        for (int e = 1; e < EE; e++) mx = fmaxf(mx, acc[e]);
        float p[EE], s = 0.f;
#pragma unroll
        for (int e = 0; e < EE; e++) { p[e] = expf(acc[e] - mx); s += p[e]; }
        int i0 = 0;
#pragma unroll
        for (int e = 1; e < EE; e++) if (p[e] > p[i0]) i0 = e;
        int i1 = (i0 == 0) ? 1 : 0;
#pragma unroll
        for (int e = 0; e < EE; e++) if (e != i0 && p[e] > p[i1]) i1 = e;
        float sc0 = p[i0] / s, sc1 = p[i1] / s;
        float inv = 1.f / (sc0 + sc1 + 1e-20f);
        g_top_idx[warp * 2 + 0] = i0;
        g_top_idx[warp * 2 + 1] = i1;
        g_top_w[warp * 2 + 0] = sc0 * inv;
        g_top_w[warp * 2 + 1] = sc1 * inv;
        atomicAdd(&g_cnt[i0], 1);
        atomicAdd(&g_cnt[i1], 1);
    }
}

__global__ void k_prefix() {
    if (threadIdx.x == 0) {
        int acc = 0;
#pragma unroll
        for (int e = 0; e < EE; e++) { g_off[e] = acc; acc += g_cnt[e]; }
        g_off[EE] = acc;
    }
    if (threadIdx.x < EE) g_pos[threadIdx.x] = 0;
}

__global__ void k_scatter() {
    int t = blockIdx.x * blockDim.x + threadIdx.x;
    if (t >= TT) return;
#pragma unroll
    for (int k = 0; k < KK; k++) {
        int e = g_top_idx[t * 2 + k];
        int s = g_off[e] + atomicAdd(&g_pos[e], 1);
        g_tok[s] = t;
        g_wt[s] = g_top_w[t * 2 + k];
        g_slot[t * 2 + k] = s;
    }
}

// ---------------- conversion kernels: globals referenced INSIDE kernels only ----------------
__device__ __forceinline__ void cvt_body(const float4* __restrict__ src,
                                         bf16* __restrict__ hi, bf16* __restrict__ lo,
                                         int i) {
    float4 v = src[i];
    uint32_t h0, l0, h1, l1;
    split2(v.x, v.y, h0, l0);
    split2(v.z, v.w, h1, l1);
    ((uint2*)hi)[i] = make_uint2(h0, h1);
    ((uint2*)lo)[i] = make_uint2(l0, l1);
}

__global__ void k_cvt_x(const float4* __restrict__ src) {
    int i = blockIdx.x * blockDim.x + threadIdx.x;
    if (i < TT * HH / 4) cvt_body(src, gxh, gxl, i);
}
__global__ void k_cvt_ws1(const float4* __restrict__ src) {
    int i = blockIdx.x * blockDim.x + threadIdx.x;
    if (i < DSS * HH / 4) cvt_body(src, gw_s1h, gw_s1l, i);
}
__global__ void k_cvt_ws2(const float4* __restrict__ src) {
    int i = blockIdx.x * blockDim.x + threadIdx.x;
    if (i < HH * DSS / 4) cvt_body(src, gw_s2h, gw_s2l, i);
}
__global__ void k_cvt_w1(const float4* __restrict__ src) {
    int i = blockIdx.x * blockDim.x + threadIdx.x;
    if (i < EE * DEE * HH / 4) cvt_body(src, gw_1h, gw_1l, i);
}
__global__ void k_cvt_w2(const float4* __restrict__ src) {
    int i = blockIdx.x * blockDim.x + threadIdx.x;
    if (i < EE * HH * DEE / 4) cvt_body(src, gw_2h, gw_2l, i);
}

// ---------------- bf16 hi/lo 3-pass mma GEMM, pre-split operands ----------------
// C[M,N] = A[M,K]*B[N,K]^T with A,B given as bf16 hi/lo pairs.
#define BM 128
#define BN 128
#define BK 16
#define NTH 256
#define APITCH 24   // bf16 units per A row (16 + 8 pad)  -> 48B rows, 16B-aligned uint4 stores
#define BPITCH 20   // bf16 units per B row (16 + 4 pad)  -> proven R14 pattern

template <int MODE, bool GATHER>   // MODE 0: relu->bf16 hi/lo; 1: fp32; 2: fp32*rowsc
__device__ __forceinline__ void gemm_tile(
    const bf16* __restrict__ Ah, const bf16* __restrict__ Al, int lda,
    const bf16* __restrict__ Bh, const bf16* __restrict__ Bl, int ldb,
    const float* __restrict__ bias, const float* __restrict__ rowsc,
    const int* __restrict__ gidx,
    float* __restrict__ Cf, bf16* __restrict__ Ch, bf16* __restrict__ Cl, int ldc,
    int Kd, int m0, int m_end, int n0)
{
    __shared__ uint16_t Ash[2][BM][APITCH];
    __shared__ uint16_t Asl[2][BM][APITCH];
    __shared__ uint16_t Bsh[2][BN][BPITCH];
    __shared__ uint16_t Bsl[2][BN][BPITCH];

    const int tid  = threadIdx.x;
    const int lane = tid & 31;
    const int wid  = tid >> 5;
    const int wm   = wid & 1;    // m half (64 rows)
    const int wn   = wid >> 1;   // n quarter (32 cols)

    float acc[4][4][4];
#pragma unroll
    for (int i = 0; i < 4; i++)
#pragma unroll
        for (int j = 0; j < 4; j++)
#pragma unroll
            for (int q = 0; q < 4; q++) acc[i][j][q] = 0.f;

    // staging map: thread -> (row, 8-elem half). 16B hi + 16B lo for A and B each.
    const int r  = tid >> 1;          // 0..127
    const int c8 = (tid & 1) * 8;     // bf16 k offset within chunk
    int gm = m0 + r;
    if (gm >= m_end) gm = m0;
    const int asrc = GATHER ? gidx[gm] : gm;
    const bf16* aBh = Ah + (size_t)asrc * lda + c8;
    const bf16* aBl = Al + (size_t)asrc * lda + c8;
    const bf16* bBh = Bh + (size_t)(n0 + r) * ldb + c8;
    const bf16* bBl = Bl + (size_t)(n0 + r) * ldb + c8;

    const int nch = Kd / BK;
    uint4 pah, pal, pbh, pbl;

    // prologue: chunk 0 -> buffer 0
    pah = *(const uint4*)(aBh);
    pal = *(const uint4*)(aBl);
    pbh = *(const uint4*)(bBh);
    pbl = *(const uint4*)(bBl);
    *(uint4*)&Ash[0][r][c8] = pah;
    *(uint4*)&Asl[0][r][c8] = pal;
    *(uint2*)&Bsh[0][r][c8]     = make_uint2(pbh.x, pbh.y);
    *(uint2*)&Bsh[0][r][c8 + 4] = make_uint2(pbh.z, pbh.w);
    *(uint2*)&Bsl[0][r][c8]     = make_uint2(pbl.x, pbl.y);
    *(uint2*)&Bsl[0][r][c8 + 4] = make_uint2(pbl.z, pbl.w);
    __syncthreads();

    for (int kc = 0; kc < nch; kc++) {
        const bool more = (kc + 1 < nch);
        if (more) {
            const int kn = (kc + 1) * BK;
            pah = *(const uint4*)(aBh + kn);
            pal = *(const uint4*)(aBl + kn);
            pbh = *(const uint4*)(bBh + kn);
            pbl = *(const uint4*)(bBl + kn);
        }

        // ---- fragments straight from split smem (zero in-loop cvt) ----
        const int cur = kc & 1;
        const int c2  = (lane & 3) * 2;           // bf16 k index of pair start
        uint32_t ah[4][4], al[4][4], bh[4][2], bl[4][2];
#pragma unroll
        for (int mi = 0; mi < 4; mi++) {
            const int rr = wm * 64 + mi * 16 + (lane >> 2);
            ah[mi][0] = *(const uint32_t*)&Ash[cur][rr][c2];
            ah[mi][1] = *(const uint32_t*)&Ash[cur][rr + 8][c2];
            ah[mi][2] = *(const uint32_t*)&Ash[cur][rr][c2 + 8];
            ah[mi][3] = *(const uint32_t*)&Ash[cur][rr + 8][c2 + 8];
            al[mi][0] = *(const uint32_t*)&Asl[cur][rr][c2];
            al[mi][1] = *(const uint32_t*)&Asl[cur][rr + 8][c2];
            al[mi][2] = *(const uint32_t*)&Asl[cur][rr][c2 + 8];
            al[mi][3] = *(const uint32_t*)&Asl[cur][rr + 8][c2 + 8];
        }
#pragma unroll
        for (int nj = 0; nj < 4; nj++) {
            const int n = wn * 32 + nj * 8 + (lane >> 2);
            bh[nj][0] = *(const uint32_t*)&Bsh[cur][n][c2];
            bh[nj][1] = *(const uint32_t*)&Bsh[cur][n][c2 + 8];
            bl[nj][0] = *(const uint32_t*)&Bsl[cur][n][c2];
            bl[nj][1] = *(const uint32_t*)&Bsl[cur][n][c2 + 8];
        }
        // 3 passes: Ah*Bh + Ah*Bl + Al*Bh  (48 MMAs)
#pragma unroll
        for (int mi = 0; mi < 4; mi++)
#pragma unroll
            for (int nj = 0; nj < 4; nj++) {
                MMABF16(acc[mi][nj], ah[mi], bh[nj]);
                MMABF16(acc[mi][nj], ah[mi], bl[nj]);
                MMABF16(acc[mi][nj], al[mi], bh[nj]);
            }

        // ---- store prefetched chunk into other buffer ----
        if (more) {
            const int nxt = (kc + 1) & 1;
            *(uint4*)&Ash[nxt][r][c8] = pah;
            *(uint4*)&Asl[nxt][r][c8] = pal;
            *(uint2*)&Bsh[nxt][r][c8]     = make_uint2(pbh.x, pbh.y);
            *(uint2*)&Bsh[nxt][r][c8 + 4] = make_uint2(pbh.z, pbh.w);
            *(uint2*)&Bsl[nxt][r][c8]     = make_uint2(pbl.x, pbl.y);
            *(uint2*)&Bsl[nxt][r][c8 + 4] = make_uint2(pbl.z, pbl.w);
        }
        __syncthreads();
    }

    // ---- epilogue ----
#pragma unroll
    for (int mi = 0; mi < 4; mi++) {
#pragma unroll
        for (int half = 0; half < 2; half++) {
            int gmo = m0 + wm * 64 + mi * 16 + (lane >> 2) + half * 8;
            if (gmo >= m_end) continue;
            float sc = (MODE == 2) ? rowsc[gmo] : 1.f;
#pragma unroll
            for (int nj = 0; nj < 4; nj++) {
                int col = n0 + wn * 32 + nj * 8 + (lane & 3) * 2;
                float v0 = acc[mi][nj][half * 2 + 0] + bias[col];
                float v1 = acc[mi][nj][half * 2 + 1] + bias[col + 1];
                if (MODE == 0) {
                    v0 = fmaxf(v0, 0.f);
                    v1 = fmaxf(v1, 0.f);
                    uint32_t hp, lp;
                    split2(v0, v1, hp, lp);
                    *(uint32_t*)(Ch + (size_t)gmo * ldc + col) = hp;
                    *(uint32_t*)(Cl + (size_t)gmo * ldc + col) = lp;
                } else {
                    if (MODE == 2) { v0 *= sc; v1 *= sc; }
                    *(float2*)(Cf + (size_t)gmo * ldc + col) = make_float2(v0, v1);
                }
            }
        }
    }
}

// ---------------- GEMM wrappers (globals referenced inside; same grids as R14) ----------------
__global__ __launch_bounds__(NTH) void k_shared_fc1(const float* __restrict__ bs1) {
    gemm_tile<0, false>(gxh, gxl, HH, gw_s1h, gw_s1l, HH, bs1, nullptr, nullptr,
                        nullptr, ghsh, ghsl, DSS, HH, blockIdx.x * BM, TT, blockIdx.y * BN);
}

__global__ __launch_bounds__(NTH) void k_shared_fc2(const float* __restrict__ bs2,
                                                    float* __restrict__ out) {
    gemm_tile<1, false>(ghsh, ghsl, DSS, gw_s2h, gw_s2l, DSS, bs2, nullptr, nullptr,
                        out, nullptr, nullptr, HH, DSS, blockIdx.x * BM, TT, blockIdx.y * BN);
}

__global__ __launch_bounds__(NTH) void k_routed_fc1(const float* __restrict__ b1) {
    int e = blockIdx.z;
    int s0 = g_off[e], s1 = g_off[e + 1];
    int m0 = s0 + blockIdx.x * BM;
    if (m0 >= s1) return;
    gemm_tile<0, true>(gxh, gxl, HH, gw_1h + (size_t)e * DEE * HH, gw_1l + (size_t)e * DEE * HH, HH,
                       b1 + e * DEE, nullptr, g_tok,
                       nullptr, gh1h, gh1l, DEE, HH, m0, s1, 0);
}

__global__ __launch_bounds__(NTH) void k_routed_fc2(const float* __restrict__ b2) {
    int e = blockIdx.z;
    int s0 = g_off[e], s1 = g_off[e + 1];
    int m0 = s0 + blockIdx.x * BM;
    if (m0 >= s1) return;
    gemm_tile<2, false>(gh1h, gh1l, DEE, gw_2h + (size_t)e * HH * DEE, gw_2l + (size_t)e * HH * DEE, DEE,
                        b2 + (size_t)e * HH, g_wt, nullptr,
                        g_y2, nullptr, nullptr, HH, DEE, m0, s1, blockIdx.y * BN);
}

// out[t] = shared(t) + y2[slot0(t)] + y2[slot1(t)]
__global__ void k_combine(float* __restrict__ out) {
    const int n4 = HH / 4;
    int i = blockIdx.x * blockDim.x + threadIdx.x;
    if (i >= TT * n4) return;
    int t = i / n4;
    int c = i - t * n4;
    int s0 = g_slot[t * 2 + 0];
    int s1 = g_slot[t * 2 + 1];
    const float4* y = (const float4*)g_y2;
    float4 o = ((const float4*)out)[i];
    float4 a = y[(size_t)s0 * n4 + c];
    float4 b = y[(size_t)s1 * n4 + c];
    o.x += a.x + b.x;
    o.y += a.y + b.y;
    o.z += a.z + b.z;
    o.w += a.w + b.w;
    ((float4*)out)[i] = o;
}

// ---------------- launch ----------------
extern "C" void kernel_launch(void* const* d_in, const int* in_sizes, int n_in,
                              void* d_out, int out_size) {
    const float* x   = (const float*)d_in[0];
    const float* Wg  = (const float*)d_in[1];
    const float* W1  = (const float*)d_in[2];
    const float* b1  = (const float*)d_in[3];
    const float* W2  = (const float*)d_in[4];
    const float* b2  = (const float*)d_in[5];
    const float* Ws1 = (const float*)d_in[6];
    const float* bs1 = (const float*)d_in[7];
    const float* Ws2 = (const float*)d_in[8];
    const float* bs2 = (const float*)d_in[9];
    float* out = (float*)d_out;

    // pre-split x + all weights into bf16 hi/lo (globals written device-side)
    k_cvt_x  <<<(TT * HH / 4 + 255) / 256, 256>>>((const float4*)x);
    k_cvt_ws1<<<(DSS * HH / 4 + 255) / 256, 256>>>((const float4*)Ws1);
    k_cvt_ws2<<<(HH * DSS / 4 + 255) / 256, 256>>>((const float4*)Ws2);
    k_cvt_w1 <<<(EE * DEE * HH / 4 + 255) / 256, 256>>>((const float4*)W1);
    k_cvt_w2 <<<(EE * HH * DEE / 4 + 255) / 256, 256>>>((const float4*)W2);

    // gating + routing
    k_zero_cnt<<<1, 32>>>();
    k_gate<<<TT / 8, 256>>>(x, Wg);
    k_prefix<<<1, 32>>>();
    k_scatter<<<TT / 256, 256>>>();

    // GEMMs
    k_shared_fc1<<<dim3(TT / BM, DSS / BN), NTH>>>(bs1);
    k_routed_fc1<<<dim3(NSLOT / BM, 1, EE), NTH>>>(b1);
    k_shared_fc2<<<dim3(TT / BM, HH / BN),  NTH>>>(bs2, out);
    k_routed_fc2<<<dim3(NSLOT / BM, HH / BN, EE), NTH>>>(b2);

    k_combine<<<(TT * (HH / 4) + 255) / 256, 256>>>(out);
}